// round 5
// baseline (speedup 1.0000x reference)
#include <cuda_runtime.h>
#include <cstdint>

#define VOCAB 32000
#define EMB   256
#define UNITS 1024
#define BATCH 64
#define TLEN  512
#define N3    3072

#define GRID  128
#define TPB   512
#define NCHUNK 8           // k chunks of 128

// -------------------- device globals (no allocation allowed) ---------------
__device__ float g_xproj[(size_t)BATCH * TLEN * N3];            // [B*T, 3U]
__device__ __align__(16) uint32_t g_hx[BATCH * UNITS];          // h  (tf32 bits)
__device__ __align__(16) uint32_t g_rhx[BATCH * UNITS];         // r*h (tf32 bits)
__device__ unsigned g_count = 0;

// -------------------- helpers ----------------------------------------------
__device__ __forceinline__ uint32_t f2tf32(float x) {
    uint32_t r;
    asm("cvt.rna.tf32.f32 %0, %1;" : "=r"(r) : "f"(x));
    return r;
}

__device__ __forceinline__ uint32_t s2u(const void* p) {
    uint32_t a;
    asm("{ .reg .u64 t; cvta.to.shared.u64 t, %1; cvt.u32.u64 %0, t; }"
        : "=r"(a) : "l"(p));
    return a;
}

__device__ __forceinline__ void cp_async16(uint32_t saddr, const void* gaddr) {
    asm volatile("cp.async.cg.shared.global [%0], [%1], 16;"
                 :: "r"(saddr), "l"(gaddr));
}
#define CP_COMMIT() asm volatile("cp.async.commit_group;")
#define CP_WAIT0()  asm volatile("cp.async.wait_group 0;")
#define CP_WAIT1()  asm volatile("cp.async.wait_group 1;")
#define CP_WAIT2()  asm volatile("cp.async.wait_group 2;")

#define MMA_TF32(d0,d1,d2,d3,a0,a1,a2,a3,b0,b1)                               \
    asm volatile(                                                             \
        "mma.sync.aligned.m16n8k8.row.col.f32.tf32.tf32.f32 "                 \
        "{%0,%1,%2,%3},{%4,%5,%6,%7},{%8,%9},{%0,%1,%2,%3};"                  \
        : "+f"(d0), "+f"(d1), "+f"(d2), "+f"(d3)                              \
        : "r"(a0), "r"(a1), "r"(a2), "r"(a3), "r"(b0), "r"(b1))

// -------------------- grid barrier: monotonic release/acquire --------------
__device__ __forceinline__ void grid_barrier(unsigned target)
{
    __syncthreads();
    if (threadIdx.x == 0) {
        unsigned* cnt = &g_count;
        asm volatile("red.release.gpu.global.add.u32 [%0], %1;"
                     :: "l"(cnt), "r"(1u) : "memory");
        unsigned v;
        do {
            asm volatile("ld.acquire.gpu.global.u32 %0, [%1];"
                         : "=r"(v) : "l"(cnt) : "memory");
        } while (v < target);
    }
    __syncthreads();
}

// ---------------------------------------------------------------------------
// Kernel 1: xproj = gather(emb_table, x) @ kernel + bias  — tf32 mma.sync
// (verified in R4; adds g_count reset for replay determinism)
// ---------------------------------------------------------------------------
__global__ __launch_bounds__(256) void xproj_tf32(
    const int* __restrict__ x,
    const float* __restrict__ emb_table,
    const float* __restrict__ kernelW,
    const float* __restrict__ bias)
{
    if (blockIdx.x == 0 && blockIdx.y == 0 && threadIdx.x == 0)
        g_count = 0;

    __shared__ uint32_t As[128 * 20];
    __shared__ uint32_t Bs[128 * 20];

    const int tid  = threadIdx.x;
    const int wid  = tid >> 5;
    const int lane = tid & 31;
    const int gID  = lane >> 2;
    const int tig  = lane & 3;
    const int wm   = wid & 1;
    const int wn   = wid >> 1;

    const int m0 = blockIdx.y * 128;
    const int n0 = blockIdx.x * 128;

    const int arow = tid & 127;
    const int akq  = tid >> 7;
    const int token = x[m0 + arow];
    const float* aptr = emb_table + (size_t)token * EMB;

    const int bk = tid >> 4;
    const int bq = tid & 15;

    float acc[4][4][4];
#pragma unroll
    for (int mi = 0; mi < 4; mi++)
#pragma unroll
        for (int ni = 0; ni < 4; ni++)
#pragma unroll
            for (int c = 0; c < 4; c++) acc[mi][ni][c] = 0.f;

    for (int k0 = 0; k0 < EMB; k0 += 16) {
        float4 a0 = *(const float4*)(aptr + k0 + akq * 8);
        float4 a1 = *(const float4*)(aptr + k0 + akq * 8 + 4);
        const float* wr = kernelW + (size_t)(k0 + bk) * N3 + n0 + bq * 8;
        float4 b0 = *(const float4*)wr;
        float4 b1 = *(const float4*)(wr + 4);

        __syncthreads();
        uint32_t* ad = &As[arow * 20 + akq * 8];
        ad[0] = f2tf32(a0.x); ad[1] = f2tf32(a0.y);
        ad[2] = f2tf32(a0.z); ad[3] = f2tf32(a0.w);
        ad[4] = f2tf32(a1.x); ad[5] = f2tf32(a1.y);
        ad[6] = f2tf32(a1.z); ad[7] = f2tf32(a1.w);
        Bs[(bq * 8 + 0) * 20 + bk] = f2tf32(b0.x);
        Bs[(bq * 8 + 1) * 20 + bk] = f2tf32(b0.y);
        Bs[(bq * 8 + 2) * 20 + bk] = f2tf32(b0.z);
        Bs[(bq * 8 + 3) * 20 + bk] = f2tf32(b0.w);
        Bs[(bq * 8 + 4) * 20 + bk] = f2tf32(b1.x);
        Bs[(bq * 8 + 5) * 20 + bk] = f2tf32(b1.y);
        Bs[(bq * 8 + 6) * 20 + bk] = f2tf32(b1.z);
        Bs[(bq * 8 + 7) * 20 + bk] = f2tf32(b1.w);
        __syncthreads();

#pragma unroll
        for (int kt = 0; kt < 2; kt++) {
            const int kb = kt * 8;
            uint32_t af[4][4], bf[4][2];
#pragma unroll
            for (int mi = 0; mi < 4; mi++) {
                const int mr = wm * 64 + mi * 16;
                af[mi][0] = As[(mr + gID    ) * 20 + kb + tig];
                af[mi][1] = As[(mr + gID + 8) * 20 + kb + tig];
                af[mi][2] = As[(mr + gID    ) * 20 + kb + tig + 4];
                af[mi][3] = As[(mr + gID + 8) * 20 + kb + tig + 4];
            }
#pragma unroll
            for (int ni = 0; ni < 4; ni++) {
                const int nb = wn * 32 + ni * 8;
                bf[ni][0] = Bs[(nb + gID) * 20 + kb + tig];
                bf[ni][1] = Bs[(nb + gID) * 20 + kb + tig + 4];
            }
#pragma unroll
            for (int mi = 0; mi < 4; mi++)
#pragma unroll
                for (int ni = 0; ni < 4; ni++)
                    MMA_TF32(acc[mi][ni][0], acc[mi][ni][1],
                             acc[mi][ni][2], acc[mi][ni][3],
                             af[mi][0], af[mi][1], af[mi][2], af[mi][3],
                             bf[ni][0], bf[ni][1]);
        }
    }

#pragma unroll
    for (int mi = 0; mi < 4; mi++) {
#pragma unroll
        for (int ni = 0; ni < 4; ni++) {
            const int row = m0 + wm * 64 + mi * 16 + gID;
            const int col = n0 + wn * 32 + ni * 8 + 2 * tig;
            const float bz0 = bias[col], bz1 = bias[col + 1];
            float2 v0 = make_float2(acc[mi][ni][0] + bz0, acc[mi][ni][1] + bz1);
            float2 v1 = make_float2(acc[mi][ni][2] + bz0, acc[mi][ni][3] + bz1);
            *(float2*)&g_xproj[(size_t)row * N3 + col]       = v0;
            *(float2*)&g_xproj[(size_t)(row + 8) * N3 + col] = v1;
        }
    }
}

// ---------------------------------------------------------------------------
// Kernel 2: persistent GRU scan — tf32 mma, 512 threads (16 warps),
// per-warp private cp.async staging (3-deep), register gate state,
// release/acquire grid barrier.
// CTA c owns units [c*8, c*8+8).
// SMEM (floats):
//   ws   [24][1028]             @ 0       Wz/Wr/Wh cols (tf32 bits)
//   stg  [16 warps][3][32][20]  @ 24672   per-warp staged h/rh slices
//   pacc (aliases stg)          @ 24672   16x544 (A) / 16x288 (B)
// total 55392 floats = 221568 B
// ---------------------------------------------------------------------------
#define SM_WS   0
#define SM_STG  24672
#define WSTG    640        // 32 rows * 20
#define SM_PACC 24672
#define SMEM_FLOATS 55392

__global__ void __launch_bounds__(TPB, 1) gru_scan(
    const float* __restrict__ hidden,
    const float* __restrict__ rk,
    float* __restrict__ out)
{
    extern __shared__ float sm[];
    uint32_t* smu = (uint32_t*)sm;
    float* pacc = sm + SM_PACC;

    const int tid  = threadIdx.x;
    const int cta  = blockIdx.x;
    const int wid  = tid >> 5;
    const int lane = tid & 31;
    const int gID  = lane >> 2;
    const int tig  = lane & 3;
    const int mg   = wid & 1;         // m-group: rows [mg*32, mg*32+32)
    const int ksl  = wid >> 1;        // k-slice 0..7 (16 k per 128-chunk)

    // epilogue mapping (stable per thread)
    const int erow = tid >> 3;        // batch row 0..63
    const int eu   = tid & 7;         // local unit
    const int ecol = cta * 8 + eu;
    const int ermg = erow >> 5;
    const int elr  = erow & 31;

    // ---- load weight slice to smem as tf32 (one time) ----
    for (int idx = tid; idx < 24 * 1024; idx += TPB) {
        const int r = idx >> 10;
        const int k = idx & 1023;
        const int col = (r >> 3) * UNITS + cta * 8 + (r & 7);
        smu[SM_WS + r * 1028 + k] = f2tf32(rk[(size_t)k * N3 + col]);
    }

    // ---- init g_hx (tf32 of hidden) + register h ----
    float hreg;
    {
        int gidx = cta * TPB + tid;              // 128*512 = 65536 exactly
        g_hx[gidx] = f2tf32(hidden[gidx]);
        hreg = hidden[erow * UNITS + ecol];
    }
    unsigned bseq = 0;
    grid_barrier(++bseq * GRID);

    // per-warp staging: thread stages row=lane, 4x16B slots of its warp slice
    const int grow_off = (mg * 32 + lane) * 1024 + ksl * 16;    // + kc*128 + s*4
    const uint32_t st_base = s2u(&smu[SM_STG + wid * (3 * WSTG) + lane * 20]);

    const uint32_t* wsz = &smu[SM_WS + gID * 1028];
    const uint32_t* wsr = &smu[SM_WS + (8 + gID) * 1028];
    const uint32_t* wsh = &smu[SM_WS + (16 + gID) * 1028];
    const int kwoff = ksl * 16 + tig;            // + kc*128 + i*8 (+4)

    float zreg = 0.f;

    for (int t = 0; t < TLEN; t++) {
        // prefetch gate inputs for this step (consumed in epilogues)
        const size_t xb = ((size_t)(erow * TLEN + t)) * N3 + ecol;
        const float xz = __ldcg(&g_xproj[xb]);
        const float xr = __ldcg(&g_xproj[xb + UNITS]);
        const float xh = __ldcg(&g_xproj[xb + 2 * UNITS]);

        // =================== Phase A: zr = h @ [Wz|Wr] =======================
        {
            const uint32_t* src = g_hx;

            float az[2][4], ar[2][4];
#pragma unroll
            for (int m = 0; m < 2; m++)
#pragma unroll
                for (int c = 0; c < 4; c++) { az[m][c] = 0.f; ar[m][c] = 0.f; }

            // prologue: chunks 0..2 into buffers 0..2
#pragma unroll
            for (int p = 0; p < 3; p++) {
#pragma unroll
                for (int s = 0; s < 4; s++)
                    cp_async16(st_base + p * (WSTG * 4) + s * 16,
                               src + grow_off + p * 128 + s * 4);
                CP_COMMIT();
            }

#pragma unroll
            for (int kc = 0; kc < NCHUNK; kc++) {
                if (kc < 6) { CP_WAIT2(); } else if (kc == 6) { CP_WAIT1(); } else { CP_WAIT0(); }
                __syncwarp();

                const uint32_t* stg = &smu[SM_STG + wid * (3 * WSTG) + (kc % 3) * WSTG];
                const int kg = kc * 128;
#pragma unroll
                for (int i = 0; i < 2; i++) {
                    const int c0 = i * 8 + tig;
                    uint32_t a00 = stg[(gID     ) * 20 + c0];
                    uint32_t a01 = stg[(gID +  8) * 20 + c0];
                    uint32_t a02 = stg[(gID     ) * 20 + c0 + 4];
                    uint32_t a03 = stg[(gID +  8) * 20 + c0 + 4];
                    uint32_t a10 = stg[(gID + 16) * 20 + c0];
                    uint32_t a11 = stg[(gID + 24) * 20 + c0];
                    uint32_t a12 = stg[(gID + 16) * 20 + c0 + 4];
                    uint32_t a13 = stg[(gID + 24) * 20 + c0 + 4];
                    const int kw = kg + kwoff + i * 8;
                    uint32_t bz0 = wsz[kw], bz1 = wsz[kw + 4];
                    uint32_t br0 = wsr[kw], br1 = wsr[kw + 4];
                    MMA_TF32(az[0][0], az[0][1], az[0][2], az[0][3], a00, a01, a02, a03, bz0, bz1);
                    MMA_TF32(az[1][0], az[1][1], az[1][2], az[1][3], a10, a11, a12, a13, bz0, bz1);
                    MMA_TF32(ar[0][0], ar[0][1], ar[0][2], ar[0][3], a00, a01, a02, a03, br0, br1);
                    MMA_TF32(ar[1][0], ar[1][1], ar[1][2], ar[1][3], a10, a11, a12, a13, br0, br1);
                }

                if (kc < 5) {
#pragma unroll
                    for (int s = 0; s < 4; s++)
                        cp_async16(st_base + (kc % 3) * (WSTG * 4) + s * 16,
                                   src + grow_off + (kc + 3) * 128 + s * 4);
                    CP_COMMIT();
                }
            }

            __syncthreads();   // all warps done with staging before pacc alias

            // store warp partials: C[32x16], row stride 17
            float* pw = pacc + wid * 544;
#pragma unroll
            for (int m = 0; m < 2; m++) {
                const int rb = m * 16;
                pw[(rb + gID    ) * 17 + 2 * tig    ] = az[m][0];
                pw[(rb + gID    ) * 17 + 2 * tig + 1] = az[m][1];
                pw[(rb + gID + 8) * 17 + 2 * tig    ] = az[m][2];
                pw[(rb + gID + 8) * 17 + 2 * tig + 1] = az[m][3];
                pw[(rb + gID    ) * 17 + 8 + 2 * tig    ] = ar[m][0];
                pw[(rb + gID    ) * 17 + 8 + 2 * tig + 1] = ar[m][1];
                pw[(rb + gID + 8) * 17 + 8 + 2 * tig    ] = ar[m][2];
                pw[(rb + gID + 8) * 17 + 8 + 2 * tig + 1] = ar[m][3];
            }
            __syncthreads();

            // gates: 512 outputs, 1 per thread; reduce 8 k-slices
            {
                float zp = 0.f, rp = 0.f;
#pragma unroll
                for (int s = 0; s < 8; s++) {
                    const float* p = pacc + (s * 2 + ermg) * 544 + elr * 17;
                    zp += p[eu];
                    rp += p[8 + eu];
                }
                float z = 1.f / (1.f + __expf(-(xz + zp)));
                float r = 1.f / (1.f + __expf(-(xr + rp)));
                g_rhx[erow * UNITS + ecol] = f2tf32(r * hreg);
                zreg = z;
            }
        }
        grid_barrier(++bseq * GRID);

        // =================== Phase B: m_h = rh @ Wh ==========================
        {
            const uint32_t* src = g_rhx;

            float ah[2][4];
#pragma unroll
            for (int m = 0; m < 2; m++)
#pragma unroll
                for (int c = 0; c < 4; c++) ah[m][c] = 0.f;

#pragma unroll
            for (int p = 0; p < 3; p++) {
#pragma unroll
                for (int s = 0; s < 4; s++)
                    cp_async16(st_base + p * (WSTG * 4) + s * 16,
                               src + grow_off + p * 128 + s * 4);
                CP_COMMIT();
            }

#pragma unroll
            for (int kc = 0; kc < NCHUNK; kc++) {
                if (kc < 6) { CP_WAIT2(); } else if (kc == 6) { CP_WAIT1(); } else { CP_WAIT0(); }
                __syncwarp();

                const uint32_t* stg = &smu[SM_STG + wid * (3 * WSTG) + (kc % 3) * WSTG];
                const int kg = kc * 128;
#pragma unroll
                for (int i = 0; i < 2; i++) {
                    const int c0 = i * 8 + tig;
                    uint32_t a00 = stg[(gID     ) * 20 + c0];
                    uint32_t a01 = stg[(gID +  8) * 20 + c0];
                    uint32_t a02 = stg[(gID     ) * 20 + c0 + 4];
                    uint32_t a03 = stg[(gID +  8) * 20 + c0 + 4];
                    uint32_t a10 = stg[(gID + 16) * 20 + c0];
                    uint32_t a11 = stg[(gID + 24) * 20 + c0];
                    uint32_t a12 = stg[(gID + 16) * 20 + c0 + 4];
                    uint32_t a13 = stg[(gID + 24) * 20 + c0 + 4];
                    const int kw = kg + kwoff + i * 8;
                    uint32_t bh0 = wsh[kw], bh1 = wsh[kw + 4];
                    MMA_TF32(ah[0][0], ah[0][1], ah[0][2], ah[0][3], a00, a01, a02, a03, bh0, bh1);
                    MMA_TF32(ah[1][0], ah[1][1], ah[1][2], ah[1][3], a10, a11, a12, a13, bh0, bh1);
                }

                if (kc < 5) {
#pragma unroll
                    for (int s = 0; s < 4; s++)
                        cp_async16(st_base + (kc % 3) * (WSTG * 4) + s * 16,
                                   src + grow_off + (kc + 3) * 128 + s * 4);
                    CP_COMMIT();
                }
            }

            __syncthreads();

            // store warp partials: C[32x8], row stride 9
            float* pw = pacc + wid * 288;
#pragma unroll
            for (int m = 0; m < 2; m++) {
                const int rb = m * 16;
                pw[(rb + gID    ) * 9 + 2 * tig    ] = ah[m][0];
                pw[(rb + gID    ) * 9 + 2 * tig + 1] = ah[m][1];
                pw[(rb + gID + 8) * 9 + 2 * tig    ] = ah[m][2];
                pw[(rb + gID + 8) * 9 + 2 * tig + 1] = ah[m][3];
            }
            __syncthreads();

            // h update: 512 outputs, 1 per thread
            {
                float mp = 0.f;
#pragma unroll
                for (int s = 0; s < 8; s++)
                    mp += pacc[(s * 2 + ermg) * 288 + elr * 9 + eu];

                const float a = xh + mp;
                const float hh = 1.f - 2.f / (1.f + __expf(2.f * a));  // tanh(a)
                const float hn = zreg * hreg + (1.f - zreg) * hh;
                hreg = hn;
                g_hx[erow * UNITS + ecol] = f2tf32(hn);
                out[((size_t)(erow * TLEN + t)) * UNITS + ecol] = hn;
                if (t == TLEN - 1)
                    out[(size_t)BATCH * TLEN * UNITS + (size_t)erow * UNITS + ecol] = hn;
            }
        }
        grid_barrier(++bseq * GRID);
    }
}

// ---------------------------------------------------------------------------
extern "C" void kernel_launch(void* const* d_in, const int* in_sizes, int n_in,
                              void* d_out, int out_size)
{
    const int*   x      = (const int*)d_in[0];
    const float* hidden = (const float*)d_in[1];
    const float* emb    = (const float*)d_in[2];
    const float* kern   = (const float*)d_in[3];
    const float* rk     = (const float*)d_in[4];
    const float* bias   = (const float*)d_in[5];
    float* out = (float*)d_out;

    static bool attr_set = false;
    if (!attr_set) {
        cudaFuncSetAttribute(gru_scan, cudaFuncAttributeMaxDynamicSharedMemorySize,
                             SMEM_FLOATS * sizeof(float));
        attr_set = true;
    }

    // Node 1: projection GEMM (tf32, fused embedding gather) + barrier reset
    xproj_tf32<<<dim3(N3 / 128, (BATCH * TLEN) / 128), 256>>>(x, emb, kern, bias);

    // Node 2: persistent GRU scan
    gru_scan<<<GRID, TPB, SMEM_FLOATS * sizeof(float)>>>(hidden, rk, out);
}

// round 6
// speedup vs baseline: 1.8068x; 1.8068x over previous
#include <cuda_runtime.h>
#include <cstdint>

#define VOCAB 32000
#define EMB   256
#define UNITS 1024
#define BATCH 64
#define TLEN  512
#define N3    3072

#define GRID  128
#define TPB   512
#define NCHUNK 16          // k chunks of 64

// -------------------- device globals (no allocation allowed) ---------------
__device__ float g_xproj[(size_t)BATCH * TLEN * N3];            // [B*T, 3U]
__device__ __align__(16) uint32_t g_hx[BATCH * UNITS];          // h  (tf32 bits)
__device__ __align__(16) uint32_t g_rhx[BATCH * UNITS];         // r*h (tf32 bits)
__device__ unsigned g_count = 0;

// -------------------- helpers ----------------------------------------------
__device__ __forceinline__ uint32_t f2tf32(float x) {
    uint32_t r;
    asm("cvt.rna.tf32.f32 %0, %1;" : "=r"(r) : "f"(x));
    return r;
}

__device__ __forceinline__ uint32_t s2u(const void* p) {
    uint32_t a;
    asm("{ .reg .u64 t; cvta.to.shared.u64 t, %1; cvt.u32.u64 %0, t; }"
        : "=r"(a) : "l"(p));
    return a;
}

__device__ __forceinline__ void cp_async16(uint32_t saddr, const void* gaddr) {
    asm volatile("cp.async.cg.shared.global [%0], [%1], 16;"
                 :: "r"(saddr), "l"(gaddr));
}
#define CP_COMMIT() asm volatile("cp.async.commit_group;")
#define CP_WAIT0()  asm volatile("cp.async.wait_group 0;")
#define CP_WAIT1()  asm volatile("cp.async.wait_group 1;")
#define CP_WAIT2()  asm volatile("cp.async.wait_group 2;")

#define MMA_TF32(d0,d1,d2,d3,a0,a1,a2,a3,b0,b1)                               \
    asm volatile(                                                             \
        "mma.sync.aligned.m16n8k8.row.col.f32.tf32.tf32.f32 "                 \
        "{%0,%1,%2,%3},{%4,%5,%6,%7},{%8,%9},{%0,%1,%2,%3};"                  \
        : "+f"(d0), "+f"(d1), "+f"(d2), "+f"(d3)                              \
        : "r"(a0), "r"(a1), "r"(a2), "r"(a3), "r"(b0), "r"(b1))

// -------------------- grid barrier: monotonic release/acquire --------------
__device__ __forceinline__ void grid_barrier(unsigned target)
{
    __syncthreads();
    if (threadIdx.x == 0) {
        unsigned* cnt = &g_count;
        asm volatile("red.release.gpu.global.add.u32 [%0], %1;"
                     :: "l"(cnt), "r"(1u) : "memory");
        unsigned v;
        do {
            asm volatile("ld.acquire.gpu.global.u32 %0, [%1];"
                         : "=r"(v) : "l"(cnt) : "memory");
        } while (v < target);
    }
    __syncthreads();
}

// ---------------------------------------------------------------------------
// Kernel 1: xproj = gather(emb_table, x) @ kernel + bias  — tf32 mma.sync
// (verified; resets g_count for replay determinism)
// ---------------------------------------------------------------------------
__global__ __launch_bounds__(256) void xproj_tf32(
    const int* __restrict__ x,
    const float* __restrict__ emb_table,
    const float* __restrict__ kernelW,
    const float* __restrict__ bias)
{
    if (blockIdx.x == 0 && blockIdx.y == 0 && threadIdx.x == 0)
        g_count = 0;

    __shared__ uint32_t As[128 * 20];
    __shared__ uint32_t Bs[128 * 20];

    const int tid  = threadIdx.x;
    const int wid  = tid >> 5;
    const int lane = tid & 31;
    const int gID  = lane >> 2;
    const int tig  = lane & 3;
    const int wm   = wid & 1;
    const int wn   = wid >> 1;

    const int m0 = blockIdx.y * 128;
    const int n0 = blockIdx.x * 128;

    const int arow = tid & 127;
    const int akq  = tid >> 7;
    const int token = x[m0 + arow];
    const float* aptr = emb_table + (size_t)token * EMB;

    const int bk = tid >> 4;
    const int bq = tid & 15;

    float acc[4][4][4];
#pragma unroll
    for (int mi = 0; mi < 4; mi++)
#pragma unroll
        for (int ni = 0; ni < 4; ni++)
#pragma unroll
            for (int c = 0; c < 4; c++) acc[mi][ni][c] = 0.f;

    for (int k0 = 0; k0 < EMB; k0 += 16) {
        float4 a0 = *(const float4*)(aptr + k0 + akq * 8);
        float4 a1 = *(const float4*)(aptr + k0 + akq * 8 + 4);
        const float* wr = kernelW + (size_t)(k0 + bk) * N3 + n0 + bq * 8;
        float4 b0 = *(const float4*)wr;
        float4 b1 = *(const float4*)(wr + 4);

        __syncthreads();
        uint32_t* ad = &As[arow * 20 + akq * 8];
        ad[0] = f2tf32(a0.x); ad[1] = f2tf32(a0.y);
        ad[2] = f2tf32(a0.z); ad[3] = f2tf32(a0.w);
        ad[4] = f2tf32(a1.x); ad[5] = f2tf32(a1.y);
        ad[6] = f2tf32(a1.z); ad[7] = f2tf32(a1.w);
        Bs[(bq * 8 + 0) * 20 + bk] = f2tf32(b0.x);
        Bs[(bq * 8 + 1) * 20 + bk] = f2tf32(b0.y);
        Bs[(bq * 8 + 2) * 20 + bk] = f2tf32(b0.z);
        Bs[(bq * 8 + 3) * 20 + bk] = f2tf32(b0.w);
        Bs[(bq * 8 + 4) * 20 + bk] = f2tf32(b1.x);
        Bs[(bq * 8 + 5) * 20 + bk] = f2tf32(b1.y);
        Bs[(bq * 8 + 6) * 20 + bk] = f2tf32(b1.z);
        Bs[(bq * 8 + 7) * 20 + bk] = f2tf32(b1.w);
        __syncthreads();

#pragma unroll
        for (int kt = 0; kt < 2; kt++) {
            const int kb = kt * 8;
            uint32_t af[4][4], bf[4][2];
#pragma unroll
            for (int mi = 0; mi < 4; mi++) {
                const int mr = wm * 64 + mi * 16;
                af[mi][0] = As[(mr + gID    ) * 20 + kb + tig];
                af[mi][1] = As[(mr + gID + 8) * 20 + kb + tig];
                af[mi][2] = As[(mr + gID    ) * 20 + kb + tig + 4];
                af[mi][3] = As[(mr + gID + 8) * 20 + kb + tig + 4];
            }
#pragma unroll
            for (int ni = 0; ni < 4; ni++) {
                const int nb = wn * 32 + ni * 8;
                bf[ni][0] = Bs[(nb + gID) * 20 + kb + tig];
                bf[ni][1] = Bs[(nb + gID) * 20 + kb + tig + 4];
            }
#pragma unroll
            for (int mi = 0; mi < 4; mi++)
#pragma unroll
                for (int ni = 0; ni < 4; ni++)
                    MMA_TF32(acc[mi][ni][0], acc[mi][ni][1],
                             acc[mi][ni][2], acc[mi][ni][3],
                             af[mi][0], af[mi][1], af[mi][2], af[mi][3],
                             bf[ni][0], bf[ni][1]);
        }
    }

#pragma unroll
    for (int mi = 0; mi < 4; mi++) {
#pragma unroll
        for (int ni = 0; ni < 4; ni++) {
            const int row = m0 + wm * 64 + mi * 16 + gID;
            const int col = n0 + wn * 32 + ni * 8 + 2 * tig;
            const float bz0 = bias[col], bz1 = bias[col + 1];
            float2 v0 = make_float2(acc[mi][ni][0] + bz0, acc[mi][ni][1] + bz1);
            float2 v1 = make_float2(acc[mi][ni][2] + bz0, acc[mi][ni][3] + bz1);
            *(float2*)&g_xproj[(size_t)row * N3 + col]       = v0;
            *(float2*)&g_xproj[(size_t)(row + 8) * N3 + col] = v1;
        }
    }
}

// ---------------------------------------------------------------------------
// Kernel 2: persistent GRU scan — tf32 mma, 512 threads (16 warps),
// CTA-wide COALESCED cp.async staging, 4 buffers, prefetch distance 3,
// register gate state, release/acquire grid barrier.
// CTA c owns units [c*8, c*8+8).
// SMEM (floats):
//   ws   [24][1028]        @ 0      Wz/Wr/Wh cols (tf32 bits)
//   stg  [4][64][68]       @ 24672  staged h/rh chunks (64 rows x 64 k, pad 4)
//   pacc [16][544]         @ 42080  per-warp partials (A: s17x32r; B: s9)
// total 50784 floats = 203,136 B
// ---------------------------------------------------------------------------
#define SM_WS   0
#define SM_STG  24672
#define WBUF    4352       // 64 * 68 floats per buffer
#define SM_PACC 42080
#define SMEM_FLOATS 50784

__global__ void __launch_bounds__(TPB, 1) gru_scan(
    const float* __restrict__ hidden,
    const float* __restrict__ rk,
    float* __restrict__ out)
{
    extern __shared__ float sm[];
    uint32_t* smu = (uint32_t*)sm;
    float* pacc = sm + SM_PACC;

    const int tid  = threadIdx.x;
    const int cta  = blockIdx.x;
    const int wid  = tid >> 5;
    const int lane = tid & 31;
    const int gID  = lane >> 2;
    const int tig  = lane & 3;
    const int mg   = wid & 1;         // m-group: rows [mg*32, mg*32+32)
    const int ksl  = wid >> 1;        // k-slice 0..7 (one 8k tile per 64-chunk)
    const int r0   = mg * 32 + gID;

    // epilogue mapping
    const int erow = tid >> 3;        // batch row 0..63
    const int eu   = tid & 7;
    const int ecol = cta * 8 + eu;
    const int ermg = erow >> 5;
    const int elr  = erow & 31;

    // ---- load weight slice to smem as tf32 (one time) ----
    for (int idx = tid; idx < 24 * 1024; idx += TPB) {
        const int r = idx >> 10;
        const int k = idx & 1023;
        const int col = (r >> 3) * UNITS + cta * 8 + (r & 7);
        smu[SM_WS + r * 1028 + k] = f2tf32(rk[(size_t)k * N3 + col]);
    }

    // ---- init g_hx (tf32 of hidden) + register h ----
    float hreg;
    {
        int gidx = cta * TPB + tid;
        g_hx[gidx] = f2tf32(hidden[gidx]);
        hreg = hidden[erow * UNITS + ecol];
    }
    unsigned bseq = 0;
    grid_barrier(++bseq * GRID);

    // staging: 2 x 16B per thread per 64-k chunk; COALESCED:
    // 16 consecutive threads cover one row's 256B chunk segment (2 full lines)
    int st_r[2], st_c[2];
    uint32_t st_s[2];
#pragma unroll
    for (int i = 0; i < 2; i++) {
        int flat = i * TPB + tid;               // 0..1023
        st_r[i] = flat >> 4;                    // row 0..63
        st_c[i] = flat & 15;                    // 16B slot 0..15
        st_s[i] = s2u(&smu[SM_STG + st_r[i] * 68 + st_c[i] * 4]);
    }

    const uint32_t* wsz = &smu[SM_WS + gID * 1028];
    const uint32_t* wsr = &smu[SM_WS + (8 + gID) * 1028];
    const uint32_t* wsh = &smu[SM_WS + (16 + gID) * 1028];
    const int c0 = ksl * 8 + tig;               // frag col within chunk

    float zreg = 0.f;

    for (int t = 0; t < TLEN; t++) {
        const size_t xb = ((size_t)(erow * TLEN + t)) * N3 + ecol;
        const float xz = __ldcg(&g_xproj[xb]);
        const float xr = __ldcg(&g_xproj[xb + UNITS]);
        const float xh = __ldcg(&g_xproj[xb + 2 * UNITS]);

        // =================== Phase A: zr = h @ [Wz|Wr] =======================
        {
            const uint32_t* src = g_hx;

            float az[2][4], ar[2][4];
#pragma unroll
            for (int m = 0; m < 2; m++)
#pragma unroll
                for (int c = 0; c < 4; c++) { az[m][c] = 0.f; ar[m][c] = 0.f; }

            // prologue: chunks 0..2 into buffers 0..2
#pragma unroll
            for (int p = 0; p < 3; p++) {
#pragma unroll
                for (int i = 0; i < 2; i++)
                    cp_async16(st_s[i] + p * (WBUF * 4),
                               src + st_r[i] * 1024 + p * 64 + st_c[i] * 4);
                CP_COMMIT();
            }

#pragma unroll
            for (int kc = 0; kc < NCHUNK; kc++) {
                if (kc < NCHUNK - 2)      { CP_WAIT2(); }
                else if (kc == NCHUNK - 2){ CP_WAIT1(); }
                else                      { CP_WAIT0(); }
                __syncthreads();
                if (kc + 3 < NCHUNK) {
#pragma unroll
                    for (int i = 0; i < 2; i++)
                        cp_async16(st_s[i] + ((kc + 3) & 3) * (WBUF * 4),
                                   src + st_r[i] * 1024 + (kc + 3) * 64 + st_c[i] * 4);
                    CP_COMMIT();
                }

                const uint32_t* hb = &smu[SM_STG + (kc & 3) * WBUF];
                uint32_t a00 = hb[(r0     ) * 68 + c0];
                uint32_t a01 = hb[(r0 +  8) * 68 + c0];
                uint32_t a02 = hb[(r0     ) * 68 + c0 + 4];
                uint32_t a03 = hb[(r0 +  8) * 68 + c0 + 4];
                uint32_t a10 = hb[(r0 + 16) * 68 + c0];
                uint32_t a11 = hb[(r0 + 24) * 68 + c0];
                uint32_t a12 = hb[(r0 + 16) * 68 + c0 + 4];
                uint32_t a13 = hb[(r0 + 24) * 68 + c0 + 4];
                const int kw = kc * 64 + c0;
                uint32_t bz0 = wsz[kw], bz1 = wsz[kw + 4];
                uint32_t br0 = wsr[kw], br1 = wsr[kw + 4];
                MMA_TF32(az[0][0], az[0][1], az[0][2], az[0][3], a00, a01, a02, a03, bz0, bz1);
                MMA_TF32(az[1][0], az[1][1], az[1][2], az[1][3], a10, a11, a12, a13, bz0, bz1);
                MMA_TF32(ar[0][0], ar[0][1], ar[0][2], ar[0][3], a00, a01, a02, a03, br0, br1);
                MMA_TF32(ar[1][0], ar[1][1], ar[1][2], ar[1][3], a10, a11, a12, a13, br0, br1);
            }

            __syncthreads();

            // store warp partials: C[32x16], row stride 17
            float* pw = pacc + wid * 544;
#pragma unroll
            for (int m = 0; m < 2; m++) {
                const int rb = m * 16;
                pw[(rb + gID    ) * 17 + 2 * tig    ] = az[m][0];
                pw[(rb + gID    ) * 17 + 2 * tig + 1] = az[m][1];
                pw[(rb + gID + 8) * 17 + 2 * tig    ] = az[m][2];
                pw[(rb + gID + 8) * 17 + 2 * tig + 1] = az[m][3];
                pw[(rb + gID    ) * 17 + 8 + 2 * tig    ] = ar[m][0];
                pw[(rb + gID    ) * 17 + 8 + 2 * tig + 1] = ar[m][1];
                pw[(rb + gID + 8) * 17 + 8 + 2 * tig    ] = ar[m][2];
                pw[(rb + gID + 8) * 17 + 8 + 2 * tig + 1] = ar[m][3];
            }
            __syncthreads();

            // gates: 512 outputs, 1 per thread; reduce 8 k-slices
            {
                float zp = 0.f, rp = 0.f;
#pragma unroll
                for (int s = 0; s < 8; s++) {
                    const float* p = pacc + (s * 2 + ermg) * 544 + elr * 17;
                    zp += p[eu];
                    rp += p[8 + eu];
                }
                float z = 1.f / (1.f + __expf(-(xz + zp)));
                float r = 1.f / (1.f + __expf(-(xr + rp)));
                g_rhx[erow * UNITS + ecol] = f2tf32(r * hreg);
                zreg = z;
            }
        }
        grid_barrier(++bseq * GRID);

        // =================== Phase B: m_h = rh @ Wh ==========================
        {
            const uint32_t* src = g_rhx;

            float ah[2][4];
#pragma unroll
            for (int m = 0; m < 2; m++)
#pragma unroll
                for (int c = 0; c < 4; c++) ah[m][c] = 0.f;

#pragma unroll
            for (int p = 0; p < 3; p++) {
#pragma unroll
                for (int i = 0; i < 2; i++)
                    cp_async16(st_s[i] + p * (WBUF * 4),
                               src + st_r[i] * 1024 + p * 64 + st_c[i] * 4);
                CP_COMMIT();
            }

#pragma unroll
            for (int kc = 0; kc < NCHUNK; kc++) {
                if (kc < NCHUNK - 2)      { CP_WAIT2(); }
                else if (kc == NCHUNK - 2){ CP_WAIT1(); }
                else                      { CP_WAIT0(); }
                __syncthreads();
                if (kc + 3 < NCHUNK) {
#pragma unroll
                    for (int i = 0; i < 2; i++)
                        cp_async16(st_s[i] + ((kc + 3) & 3) * (WBUF * 4),
                                   src + st_r[i] * 1024 + (kc + 3) * 64 + st_c[i] * 4);
                    CP_COMMIT();
                }

                const uint32_t* hb = &smu[SM_STG + (kc & 3) * WBUF];
                uint32_t a00 = hb[(r0     ) * 68 + c0];
                uint32_t a01 = hb[(r0 +  8) * 68 + c0];
                uint32_t a02 = hb[(r0     ) * 68 + c0 + 4];
                uint32_t a03 = hb[(r0 +  8) * 68 + c0 + 4];
                uint32_t a10 = hb[(r0 + 16) * 68 + c0];
                uint32_t a11 = hb[(r0 + 24) * 68 + c0];
                uint32_t a12 = hb[(r0 + 16) * 68 + c0 + 4];
                uint32_t a13 = hb[(r0 + 24) * 68 + c0 + 4];
                const int kw = kc * 64 + c0;
                uint32_t bh0 = wsh[kw], bh1 = wsh[kw + 4];
                MMA_TF32(ah[0][0], ah[0][1], ah[0][2], ah[0][3], a00, a01, a02, a03, bh0, bh1);
                MMA_TF32(ah[1][0], ah[1][1], ah[1][2], ah[1][3], a10, a11, a12, a13, bh0, bh1);
            }

            __syncthreads();

            // store warp partials: C[32x8], row stride 9
            float* pw = pacc + wid * 288;
#pragma unroll
            for (int m = 0; m < 2; m++) {
                const int rb = m * 16;
                pw[(rb + gID    ) * 9 + 2 * tig    ] = ah[m][0];
                pw[(rb + gID    ) * 9 + 2 * tig + 1] = ah[m][1];
                pw[(rb + gID + 8) * 9 + 2 * tig    ] = ah[m][2];
                pw[(rb + gID + 8) * 9 + 2 * tig + 1] = ah[m][3];
            }
            __syncthreads();

            // h update: 512 outputs, 1 per thread
            {
                float mp = 0.f;
#pragma unroll
                for (int s = 0; s < 8; s++)
                    mp += pacc[(s * 2 + ermg) * 288 + elr * 9 + eu];

                const float a = xh + mp;
                const float hh = 1.f - 2.f / (1.f + __expf(2.f * a));  // tanh(a)
                const float hn = zreg * hreg + (1.f - zreg) * hh;
                hreg = hn;
                g_hx[erow * UNITS + ecol] = f2tf32(hn);
                out[((size_t)(erow * TLEN + t)) * UNITS + ecol] = hn;
                if (t == TLEN - 1)
                    out[(size_t)BATCH * TLEN * UNITS + (size_t)erow * UNITS + ecol] = hn;
            }
        }
        grid_barrier(++bseq * GRID);
    }
}

// ---------------------------------------------------------------------------
extern "C" void kernel_launch(void* const* d_in, const int* in_sizes, int n_in,
                              void* d_out, int out_size)
{
    const int*   x      = (const int*)d_in[0];
    const float* hidden = (const float*)d_in[1];
    const float* emb    = (const float*)d_in[2];
    const float* kern   = (const float*)d_in[3];
    const float* rk     = (const float*)d_in[4];
    const float* bias   = (const float*)d_in[5];
    float* out = (float*)d_out;

    static bool attr_set = false;
    if (!attr_set) {
        cudaFuncSetAttribute(gru_scan, cudaFuncAttributeMaxDynamicSharedMemorySize,
                             SMEM_FLOATS * sizeof(float));
        attr_set = true;
    }

    // Node 1: projection GEMM (tf32, fused embedding gather) + barrier reset
    xproj_tf32<<<dim3(N3 / 128, (BATCH * TLEN) / 128), 256>>>(x, emb, kern, bias);

    // Node 2: persistent GRU scan
    gru_scan<<<GRID, TPB, SMEM_FLOATS * sizeof(float)>>>(hidden, rk, out);
}

// round 7
// speedup vs baseline: 2.1330x; 1.1805x over previous
#include <cuda_runtime.h>
#include <cstdint>

#define VOCAB 32000
#define EMB   256
#define UNITS 1024
#define BATCH 64
#define TLEN  512
#define N3    3072

#define GRID  128
#define TPB   512
#define NCHUNK 8           // k chunks of 64 over this CTA's 512-k half

// -------------------- device globals (no allocation allowed) ---------------
__device__ float g_xproj[(size_t)BATCH * TLEN * N3];            // [B*T, 3U]
__device__ __align__(16) uint32_t g_hx[BATCH * UNITS];          // h  (tf32 bits)
__device__ __align__(16) uint32_t g_rhx[BATCH * UNITS];         // r*h (tf32 bits)
__device__ unsigned g_count = 0;

// -------------------- helpers ----------------------------------------------
__device__ __forceinline__ uint32_t f2tf32(float x) {
    uint32_t r;
    asm("cvt.rna.tf32.f32 %0, %1;" : "=r"(r) : "f"(x));
    return r;
}

__device__ __forceinline__ uint32_t s2u(const void* p) {
    uint32_t a;
    asm("{ .reg .u64 t; cvta.to.shared.u64 t, %1; cvt.u32.u64 %0, t; }"
        : "=r"(a) : "l"(p));
    return a;
}

__device__ __forceinline__ void cp_async16(uint32_t saddr, const void* gaddr) {
    asm volatile("cp.async.cg.shared.global [%0], [%1], 16;"
                 :: "r"(saddr), "l"(gaddr));
}
#define CP_COMMIT() asm volatile("cp.async.commit_group;")
#define CP_WAIT0()  asm volatile("cp.async.wait_group 0;")
#define CP_WAIT1()  asm volatile("cp.async.wait_group 1;")
#define CP_WAIT2()  asm volatile("cp.async.wait_group 2;")

#define MMA_TF32(d0,d1,d2,d3,a0,a1,a2,a3,b0,b1)                               \
    asm volatile(                                                             \
        "mma.sync.aligned.m16n8k8.row.col.f32.tf32.tf32.f32 "                 \
        "{%0,%1,%2,%3},{%4,%5,%6,%7},{%8,%9},{%0,%1,%2,%3};"                  \
        : "+f"(d0), "+f"(d1), "+f"(d2), "+f"(d3)                              \
        : "r"(a0), "r"(a1), "r"(a2), "r"(a3), "r"(b0), "r"(b1))

#define CLUSTER_SYNC() do {                                                   \
    asm volatile("barrier.cluster.arrive.aligned;" ::: "memory");             \
    asm volatile("barrier.cluster.wait.aligned;"   ::: "memory");             \
} while (0)

// peer shared-memory read (cluster rank `rank`)
__device__ __forceinline__ float dsmem_ld(uint32_t saddr, uint32_t rank) {
    uint32_t ra;
    asm("mapa.shared::cluster.u32 %0, %1, %2;" : "=r"(ra) : "r"(saddr), "r"(rank));
    float v;
    asm volatile("ld.shared::cluster.f32 %0, [%1];" : "=f"(v) : "r"(ra));
    return v;
}

// -------------------- grid barrier: monotonic release/acquire --------------
__device__ __forceinline__ void grid_barrier(unsigned target)
{
    __syncthreads();
    if (threadIdx.x == 0) {
        unsigned* cnt = &g_count;
        asm volatile("red.release.gpu.global.add.u32 [%0], %1;"
                     :: "l"(cnt), "r"(1u) : "memory");
        unsigned v;
        do {
            asm volatile("ld.acquire.gpu.global.u32 %0, [%1];"
                         : "=r"(v) : "l"(cnt) : "memory");
        } while (v < target);
    }
    __syncthreads();
}

// ---------------------------------------------------------------------------
// Kernel 1: xproj = gather(emb_table, x) @ kernel + bias  — tf32 mma.sync
// (verified; resets g_count for replay determinism)
// ---------------------------------------------------------------------------
__global__ __launch_bounds__(256) void xproj_tf32(
    const int* __restrict__ x,
    const float* __restrict__ emb_table,
    const float* __restrict__ kernelW,
    const float* __restrict__ bias)
{
    if (blockIdx.x == 0 && blockIdx.y == 0 && threadIdx.x == 0)
        g_count = 0;

    __shared__ uint32_t As[128 * 20];
    __shared__ uint32_t Bs[128 * 20];

    const int tid  = threadIdx.x;
    const int wid  = tid >> 5;
    const int lane = tid & 31;
    const int gID  = lane >> 2;
    const int tig  = lane & 3;
    const int wm   = wid & 1;
    const int wn   = wid >> 1;

    const int m0 = blockIdx.y * 128;
    const int n0 = blockIdx.x * 128;

    const int arow = tid & 127;
    const int akq  = tid >> 7;
    const int token = x[m0 + arow];
    const float* aptr = emb_table + (size_t)token * EMB;

    const int bk = tid >> 4;
    const int bq = tid & 15;

    float acc[4][4][4];
#pragma unroll
    for (int mi = 0; mi < 4; mi++)
#pragma unroll
        for (int ni = 0; ni < 4; ni++)
#pragma unroll
            for (int c = 0; c < 4; c++) acc[mi][ni][c] = 0.f;

    for (int k0 = 0; k0 < EMB; k0 += 16) {
        float4 a0 = *(const float4*)(aptr + k0 + akq * 8);
        float4 a1 = *(const float4*)(aptr + k0 + akq * 8 + 4);
        const float* wr = kernelW + (size_t)(k0 + bk) * N3 + n0 + bq * 8;
        float4 b0 = *(const float4*)wr;
        float4 b1 = *(const float4*)(wr + 4);

        __syncthreads();
        uint32_t* ad = &As[arow * 20 + akq * 8];
        ad[0] = f2tf32(a0.x); ad[1] = f2tf32(a0.y);
        ad[2] = f2tf32(a0.z); ad[3] = f2tf32(a0.w);
        ad[4] = f2tf32(a1.x); ad[5] = f2tf32(a1.y);
        ad[6] = f2tf32(a1.z); ad[7] = f2tf32(a1.w);
        Bs[(bq * 8 + 0) * 20 + bk] = f2tf32(b0.x);
        Bs[(bq * 8 + 1) * 20 + bk] = f2tf32(b0.y);
        Bs[(bq * 8 + 2) * 20 + bk] = f2tf32(b0.z);
        Bs[(bq * 8 + 3) * 20 + bk] = f2tf32(b0.w);
        Bs[(bq * 8 + 4) * 20 + bk] = f2tf32(b1.x);
        Bs[(bq * 8 + 5) * 20 + bk] = f2tf32(b1.y);
        Bs[(bq * 8 + 6) * 20 + bk] = f2tf32(b1.z);
        Bs[(bq * 8 + 7) * 20 + bk] = f2tf32(b1.w);
        __syncthreads();

#pragma unroll
        for (int kt = 0; kt < 2; kt++) {
            const int kb = kt * 8;
            uint32_t af[4][4], bf[4][2];
#pragma unroll
            for (int mi = 0; mi < 4; mi++) {
                const int mr = wm * 64 + mi * 16;
                af[mi][0] = As[(mr + gID    ) * 20 + kb + tig];
                af[mi][1] = As[(mr + gID + 8) * 20 + kb + tig];
                af[mi][2] = As[(mr + gID    ) * 20 + kb + tig + 4];
                af[mi][3] = As[(mr + gID + 8) * 20 + kb + tig + 4];
            }
#pragma unroll
            for (int ni = 0; ni < 4; ni++) {
                const int nb = wn * 32 + ni * 8;
                bf[ni][0] = Bs[(nb + gID) * 20 + kb + tig];
                bf[ni][1] = Bs[(nb + gID) * 20 + kb + tig + 4];
            }
#pragma unroll
            for (int mi = 0; mi < 4; mi++)
#pragma unroll
                for (int ni = 0; ni < 4; ni++)
                    MMA_TF32(acc[mi][ni][0], acc[mi][ni][1],
                             acc[mi][ni][2], acc[mi][ni][3],
                             af[mi][0], af[mi][1], af[mi][2], af[mi][3],
                             bf[ni][0], bf[ni][1]);
        }
    }

#pragma unroll
    for (int mi = 0; mi < 4; mi++) {
#pragma unroll
        for (int ni = 0; ni < 4; ni++) {
            const int row = m0 + wm * 64 + mi * 16 + gID;
            const int col = n0 + wn * 32 + ni * 8 + 2 * tig;
            const float bz0 = bias[col], bz1 = bias[col + 1];
            float2 v0 = make_float2(acc[mi][ni][0] + bz0, acc[mi][ni][1] + bz1);
            float2 v1 = make_float2(acc[mi][ni][2] + bz0, acc[mi][ni][3] + bz1);
            *(float2*)&g_xproj[(size_t)row * N3 + col]       = v0;
            *(float2*)&g_xproj[(size_t)(row + 8) * N3 + col] = v1;
        }
    }
}

// ---------------------------------------------------------------------------
// Kernel 2: persistent GRU scan — cluster-2 split-K.
// 128 CTAs = 64 clusters x 2. CTA (cg, crank): gate cols [cg*16, cg*16+16),
// k-half [crank*512, crank*512+512). Partial sums exchanged via DSMEM.
// SMEM (floats):
//   ws   [48][516]   @ 0      Wz(0-15)/Wr(16-31)/Wh(32-47) cols, tf32, k-half
//   stg  [4][64][68] @ 24768  staged h/rh chunks (64 rows x 64 k, pad 4)
//   pacc (alias stg) @ 24768  16x528 (A) / 16x272 (B)
//   redA [64][33]    @ 42176  reduced half-K partials (z|r), peer-readable
//   redB [64][17]    @ 44288
// total 45376 floats = 181,504 B
// ---------------------------------------------------------------------------
#define SM_WS   0
#define SM_STG  24768
#define WBUF    4352       // 64 * 68 floats per buffer
#define SM_PACC 24768
#define SM_REDA 42176
#define SM_REDB 44288
#define SMEM_FLOATS 45376

__global__ void __launch_bounds__(TPB, 1) __cluster_dims__(2, 1, 1)
gru_scan(const float* __restrict__ hidden,
         const float* __restrict__ rk,
         float* __restrict__ out)
{
    extern __shared__ float sm[];
    uint32_t* smu = (uint32_t*)sm;
    float* pacc = sm + SM_PACC;
    float* redA = sm + SM_REDA;
    float* redB = sm + SM_REDB;

    const int tid   = threadIdx.x;
    const int cta   = blockIdx.x;
    const int crank = cta & 1;        // cluster rank (k-half owner)
    const int cg    = cta >> 1;       // column group 0..63
    const uint32_t peer = crank ^ 1;

    const int wid  = tid >> 5;
    const int lane = tid & 31;
    const int gID  = lane >> 2;
    const int tig  = lane & 3;
    const int mg   = wid & 3;         // m-group: rows [mg*16, mg*16+16)
    const int ksl  = wid >> 2;        // k-slice 0..3 (16 k per 64-chunk)
    const int r0   = mg * 16 + gID;

    // gate/update mapping: thread -> (row, col), 32 rows x 16 cols per CTA
    const int grow = crank * 32 + (tid >> 4);   // global batch row
    const int gcol = cg * 16 + (tid & 15);      // global unit
    const int lcol = tid & 15;                  // local col 0..15

    // reduction mapping (all 64 rows kept for peer)
    const int rrow = tid >> 3;        // 0..63
    const int rc4  = (tid & 7) * 4;   // 4 cols (phase A)
    const int rc2  = (tid & 7) * 2;   // 2 cols (phase B)
    const int rmgr = rrow >> 4;
    const int rlr  = rrow & 15;

    // ---- load this CTA's weight slice (16 cols x 3 gates x 512 k) ----
    for (int idx = tid; idx < 48 * 512; idx += TPB) {
        const int r = idx >> 9;                  // ws row 0..47
        const int k = idx & 511;
        const int col = (r >> 4) * UNITS + cg * 16 + (r & 15);
        smu[SM_WS + r * 516 + k] = f2tf32(rk[(size_t)(crank * 512 + k) * N3 + col]);
    }

    // ---- init g_hx (tf32 of hidden) + register h ----
    float hreg;
    {
        int gidx = cta * TPB + tid;              // 128*512 = 65536 exactly
        g_hx[gidx] = f2tf32(hidden[gidx]);
        hreg = hidden[grow * UNITS + gcol];
    }
    unsigned bseq = 0;
    grid_barrier(++bseq * GRID);

    // staging: 2 x 16B per thread per 64-k chunk, coalesced
    int st_r[2], st_c[2];
    uint32_t st_s[2];
#pragma unroll
    for (int i = 0; i < 2; i++) {
        int flat = i * TPB + tid;               // 0..1023
        st_r[i] = flat >> 4;                    // row 0..63
        st_c[i] = flat & 15;                    // 16B slot 0..15
        st_s[i] = s2u(&smu[SM_STG + st_r[i] * 68 + st_c[i] * 4]);
    }
    const int koff = crank * 512;               // global k base for this CTA

    const uint32_t* wsz0 = &smu[SM_WS + (gID     ) * 516];
    const uint32_t* wsz1 = &smu[SM_WS + (gID +  8) * 516];
    const uint32_t* wsr0 = &smu[SM_WS + (gID + 16) * 516];
    const uint32_t* wsr1 = &smu[SM_WS + (gID + 24) * 516];
    const uint32_t* wsh0 = &smu[SM_WS + (gID + 32) * 516];
    const uint32_t* wsh1 = &smu[SM_WS + (gID + 40) * 516];

    float zreg = 0.f;

    for (int t = 0; t < TLEN; t++) {
        const size_t xb = ((size_t)(grow * TLEN + t)) * N3 + gcol;
        const float xz = __ldcg(&g_xproj[xb]);
        const float xr = __ldcg(&g_xproj[xb + UNITS]);
        const float xh = __ldcg(&g_xproj[xb + 2 * UNITS]);

        // =================== Phase A: zr_partial = h @ [Wz|Wr] (half-K) ======
        {
            const uint32_t* src = g_hx;

            float az0[4], az1[4], ar0[4], ar1[4];
#pragma unroll
            for (int c = 0; c < 4; c++) { az0[c]=0.f; az1[c]=0.f; ar0[c]=0.f; ar1[c]=0.f; }

#pragma unroll
            for (int p = 0; p < 3; p++) {
#pragma unroll
                for (int i = 0; i < 2; i++)
                    cp_async16(st_s[i] + p * (WBUF * 4),
                               src + st_r[i] * 1024 + koff + p * 64 + st_c[i] * 4);
                CP_COMMIT();
            }

#pragma unroll
            for (int kc = 0; kc < NCHUNK; kc++) {
                if (kc < NCHUNK - 2)      { CP_WAIT2(); }
                else if (kc == NCHUNK - 2){ CP_WAIT1(); }
                else                      { CP_WAIT0(); }
                __syncthreads();
                if (kc + 3 < NCHUNK) {
#pragma unroll
                    for (int i = 0; i < 2; i++)
                        cp_async16(st_s[i] + ((kc + 3) & 3) * (WBUF * 4),
                                   src + st_r[i] * 1024 + koff + (kc + 3) * 64 + st_c[i] * 4);
                    CP_COMMIT();
                }

                const uint32_t* hb = &smu[SM_STG + (kc & 3) * WBUF];
#pragma unroll
                for (int kt = 0; kt < 2; kt++) {
                    const int c0 = ksl * 16 + kt * 8 + tig;
                    uint32_t a0 = hb[(r0    ) * 68 + c0];
                    uint32_t a1 = hb[(r0 + 8) * 68 + c0];
                    uint32_t a2 = hb[(r0    ) * 68 + c0 + 4];
                    uint32_t a3 = hb[(r0 + 8) * 68 + c0 + 4];
                    const int kw = kc * 64 + ksl * 16 + kt * 8 + tig;
                    MMA_TF32(az0[0], az0[1], az0[2], az0[3], a0, a1, a2, a3, wsz0[kw], wsz0[kw + 4]);
                    MMA_TF32(az1[0], az1[1], az1[2], az1[3], a0, a1, a2, a3, wsz1[kw], wsz1[kw + 4]);
                    MMA_TF32(ar0[0], ar0[1], ar0[2], ar0[3], a0, a1, a2, a3, wsr0[kw], wsr0[kw + 4]);
                    MMA_TF32(ar1[0], ar1[1], ar1[2], ar1[3], a0, a1, a2, a3, wsr1[kw], wsr1[kw + 4]);
                }
            }

            __syncthreads();   // staging done before pacc alias

            // warp partials: C[16x32], row stride 33
            float* pw = pacc + wid * 528;
            pw[(gID    ) * 33 +  0 + 2 * tig    ] = az0[0];
            pw[(gID    ) * 33 +  0 + 2 * tig + 1] = az0[1];
            pw[(gID + 8) * 33 +  0 + 2 * tig    ] = az0[2];
            pw[(gID + 8) * 33 +  0 + 2 * tig + 1] = az0[3];
            pw[(gID    ) * 33 +  8 + 2 * tig    ] = az1[0];
            pw[(gID    ) * 33 +  8 + 2 * tig + 1] = az1[1];
            pw[(gID + 8) * 33 +  8 + 2 * tig    ] = az1[2];
            pw[(gID + 8) * 33 +  8 + 2 * tig + 1] = az1[3];
            pw[(gID    ) * 33 + 16 + 2 * tig    ] = ar0[0];
            pw[(gID    ) * 33 + 16 + 2 * tig + 1] = ar0[1];
            pw[(gID + 8) * 33 + 16 + 2 * tig    ] = ar0[2];
            pw[(gID + 8) * 33 + 16 + 2 * tig + 1] = ar0[3];
            pw[(gID    ) * 33 + 24 + 2 * tig    ] = ar1[0];
            pw[(gID    ) * 33 + 24 + 2 * tig + 1] = ar1[1];
            pw[(gID + 8) * 33 + 24 + 2 * tig    ] = ar1[2];
            pw[(gID + 8) * 33 + 24 + 2 * tig + 1] = ar1[3];
            __syncthreads();

            // reduce 4 k-slices -> redA[64][33] (z cols 0-15, r cols 16-31)
            {
                float s0 = 0.f, s1 = 0.f, s2 = 0.f, s3 = 0.f;
#pragma unroll
                for (int s = 0; s < 4; s++) {
                    const float* p = pacc + (s * 4 + rmgr) * 528 + rlr * 33 + rc4;
                    s0 += p[0]; s1 += p[1]; s2 += p[2]; s3 += p[3];
                }
                float* rd = redA + rrow * 33 + rc4;
                rd[0] = s0; rd[1] = s1; rd[2] = s2; rd[3] = s3;
            }
            CLUSTER_SYNC();

            // gates: own half-K partial + peer half-K partial (DSMEM)
            {
                const uint32_t zloc = s2u(&redA[grow * 33 + lcol]);
                const uint32_t rloc = s2u(&redA[grow * 33 + 16 + lcol]);
                float zp = sm[SM_REDA + grow * 33 + lcol]      + dsmem_ld(zloc, peer);
                float rp = sm[SM_REDA + grow * 33 + 16 + lcol] + dsmem_ld(rloc, peer);
                float z = 1.f / (1.f + __expf(-(xz + zp)));
                float r = 1.f / (1.f + __expf(-(xr + rp)));
                g_rhx[grow * UNITS + gcol] = f2tf32(r * hreg);
                zreg = z;
            }
        }
        grid_barrier(++bseq * GRID);

        // =================== Phase B: mh_partial = rh @ Wh (half-K) ==========
        {
            const uint32_t* src = g_rhx;

            float ah0[4], ah1[4];
#pragma unroll
            for (int c = 0; c < 4; c++) { ah0[c] = 0.f; ah1[c] = 0.f; }

#pragma unroll
            for (int p = 0; p < 3; p++) {
#pragma unroll
                for (int i = 0; i < 2; i++)
                    cp_async16(st_s[i] + p * (WBUF * 4),
                               src + st_r[i] * 1024 + koff + p * 64 + st_c[i] * 4);
                CP_COMMIT();
            }

#pragma unroll
            for (int kc = 0; kc < NCHUNK; kc++) {
                if (kc < NCHUNK - 2)      { CP_WAIT2(); }
                else if (kc == NCHUNK - 2){ CP_WAIT1(); }
                else                      { CP_WAIT0(); }
                __syncthreads();
                if (kc + 3 < NCHUNK) {
#pragma unroll
                    for (int i = 0; i < 2; i++)
                        cp_async16(st_s[i] + ((kc + 3) & 3) * (WBUF * 4),
                                   src + st_r[i] * 1024 + koff + (kc + 3) * 64 + st_c[i] * 4);
                    CP_COMMIT();
                }

                const uint32_t* hb = &smu[SM_STG + (kc & 3) * WBUF];
#pragma unroll
                for (int kt = 0; kt < 2; kt++) {
                    const int c0 = ksl * 16 + kt * 8 + tig;
                    uint32_t a0 = hb[(r0    ) * 68 + c0];
                    uint32_t a1 = hb[(r0 + 8) * 68 + c0];
                    uint32_t a2 = hb[(r0    ) * 68 + c0 + 4];
                    uint32_t a3 = hb[(r0 + 8) * 68 + c0 + 4];
                    const int kw = kc * 64 + ksl * 16 + kt * 8 + tig;
                    MMA_TF32(ah0[0], ah0[1], ah0[2], ah0[3], a0, a1, a2, a3, wsh0[kw], wsh0[kw + 4]);
                    MMA_TF32(ah1[0], ah1[1], ah1[2], ah1[3], a0, a1, a2, a3, wsh1[kw], wsh1[kw + 4]);
                }
            }

            __syncthreads();

            // warp partials: C[16x16], row stride 17
            float* pw = pacc + wid * 272;
            pw[(gID    ) * 17 + 0 + 2 * tig    ] = ah0[0];
            pw[(gID    ) * 17 + 0 + 2 * tig + 1] = ah0[1];
            pw[(gID + 8) * 17 + 0 + 2 * tig    ] = ah0[2];
            pw[(gID + 8) * 17 + 0 + 2 * tig + 1] = ah0[3];
            pw[(gID    ) * 17 + 8 + 2 * tig    ] = ah1[0];
            pw[(gID    ) * 17 + 8 + 2 * tig + 1] = ah1[1];
            pw[(gID + 8) * 17 + 8 + 2 * tig    ] = ah1[2];
            pw[(gID + 8) * 17 + 8 + 2 * tig + 1] = ah1[3];
            __syncthreads();

            // reduce 4 k-slices -> redB[64][17]
            {
                float s0 = 0.f, s1 = 0.f;
#pragma unroll
                for (int s = 0; s < 4; s++) {
                    const float* p = pacc + (s * 4 + rmgr) * 272 + rlr * 17 + rc2;
                    s0 += p[0]; s1 += p[1];
                }
                float* rd = redB + rrow * 17 + rc2;
                rd[0] = s0; rd[1] = s1;
            }
            CLUSTER_SYNC();

            // h update: own + peer partial
            {
                const uint32_t hlocA = s2u(&redB[grow * 17 + lcol]);
                float mp = sm[SM_REDB + grow * 17 + lcol] + dsmem_ld(hlocA, peer);
                const float a = xh + mp;
                const float hh = 1.f - 2.f / (1.f + __expf(2.f * a));  // tanh(a)
                const float hn = zreg * hreg + (1.f - zreg) * hh;
                hreg = hn;
                g_hx[grow * UNITS + gcol] = f2tf32(hn);
                out[((size_t)(grow * TLEN + t)) * UNITS + gcol] = hn;
                if (t == TLEN - 1)
                    out[(size_t)BATCH * TLEN * UNITS + (size_t)grow * UNITS + gcol] = hn;
            }
        }
        grid_barrier(++bseq * GRID);
    }
}

// ---------------------------------------------------------------------------
extern "C" void kernel_launch(void* const* d_in, const int* in_sizes, int n_in,
                              void* d_out, int out_size)
{
    const int*   x      = (const int*)d_in[0];
    const float* hidden = (const float*)d_in[1];
    const float* emb    = (const float*)d_in[2];
    const float* kern   = (const float*)d_in[3];
    const float* rk     = (const float*)d_in[4];
    const float* bias   = (const float*)d_in[5];
    float* out = (float*)d_out;

    static bool attr_set = false;
    if (!attr_set) {
        cudaFuncSetAttribute(gru_scan, cudaFuncAttributeMaxDynamicSharedMemorySize,
                             SMEM_FLOATS * sizeof(float));
        attr_set = true;
    }

    // Node 1: projection GEMM (tf32, fused embedding gather) + barrier reset
    xproj_tf32<<<dim3(N3 / 128, (BATCH * TLEN) / 128), 256>>>(x, emb, kern, bias);

    // Node 2: persistent GRU scan (cluster-2 split-K)
    gru_scan<<<GRID, TPB, SMEM_FLOATS * sizeof(float)>>>(hidden, rk, out);
}